// round 16
// baseline (speedup 1.0000x reference)
#include <cuda_runtime.h>
#include <cuda_bf16.h>
#include <cstdint>

// Problem constants
#define BATCH 4
#define LSEQ  1024
#define DMODEL 1024
#define NHEAD 16
#define HDIM  64
#define QKVLD (3 * DMODEL)   // 3072

// ---------------------------------------------------------------------------
// Scratch (device globals — allocation-free kernel_launch)
// ---------------------------------------------------------------------------
__device__ float g_qkv[(size_t)BATCH * LSEQ * 3 * DMODEL];        // 50 MB

// split-bf16 operands for tensor-core GEMMs
__device__ __nv_bfloat16 g_ah[(size_t)BATCH * LSEQ * DMODEL];     // x hi
__device__ __nv_bfloat16 g_al[(size_t)BATCH * LSEQ * DMODEL];     // x lo
__device__ __nv_bfloat16 g_oh[(size_t)BATCH * LSEQ * DMODEL];     // attn out hi (written by fa)
__device__ __nv_bfloat16 g_ol[(size_t)BATCH * LSEQ * DMODEL];     // attn out lo
__device__ __nv_bfloat16 g_wqh[(size_t)QKVLD * DMODEL];           // w_qkv^T hi  [3072,1024]
__device__ __nv_bfloat16 g_wql[(size_t)QKVLD * DMODEL];           // w_qkv^T lo
__device__ __nv_bfloat16 g_woh[(size_t)DMODEL * DMODEL];          // w_out^T hi  [1024,1024]
__device__ __nv_bfloat16 g_wol[(size_t)DMODEL * DMODEL];          // w_out^T lo

// ---------------------------------------------------------------------------
// PTX helpers — ONLY non-arch-'a' features (ldmatrix / mma.sync / cp.async)
// ---------------------------------------------------------------------------
__device__ __forceinline__ uint32_t smem_u32(const void* p) {
    uint32_t a;
    asm("{ .reg .u64 t; cvta.to.shared.u64 t, %1; cvt.u32.u64 %0, t; }" : "=r"(a) : "l"(p));
    return a;
}

#define CP_ASYNC16(s, g) \
    asm volatile("cp.async.cg.shared.global [%0], [%1], 16;" :: "r"(s), "l"(g))
#define CP_COMMIT() asm volatile("cp.async.commit_group;" ::: "memory")
#define CP_WAIT(n)  asm volatile("cp.async.wait_group %0;" :: "n"(n) : "memory")

#define LDSM4(r, addr)                                                       \
    asm volatile("ldmatrix.sync.aligned.m8n8.x4.shared.b16 {%0,%1,%2,%3}, [%4];" \
        : "=r"((r)[0]), "=r"((r)[1]), "=r"((r)[2]), "=r"((r)[3]) : "r"(addr))

#define MMA16816(d, a, b)                                                    \
    asm volatile("mma.sync.aligned.m16n8k16.row.col.f32.bf16.bf16.f32 "      \
        "{%0,%1,%2,%3}, {%4,%5,%6,%7}, {%8,%9}, {%0,%1,%2,%3};"              \
        : "+f"((d)[0]), "+f"((d)[1]), "+f"((d)[2]), "+f"((d)[3])             \
        : "r"((a)[0]), "r"((a)[1]), "r"((a)[2]), "r"((a)[3]),                \
          "r"((b)[0]), "r"((b)[1]))

__device__ __forceinline__ uint32_t pack_bf16(float a, float b) {
    __nv_bfloat162 h = __nv_bfloat162(__float2bfloat16(a), __float2bfloat16(b));
    return *(uint32_t*)&h;
}

// ---------------------------------------------------------------------------
// Tensor-core split-bf16 GEMM v2: C[M,N] = A[M,K] @ Bt[N,K]^T
//   3-stage cp.async pipeline, ONE __syncthreads per k-iter.
//   CTA tile 128x128, BK=32, 8 warps (4x2), warp tile 32x64.
//   3-term split: Ah*Bh + Ah*Bl + Al*Bh
// ---------------------------------------------------------------------------
#define ROWB     80
#define TILE_SB  (128 * ROWB)          // 10240 B per operand tile
#define STAGE_SB (4 * TILE_SB)         // Ah, Al, Bh, Bl = 40960 B
#define NSTAGE   3
#define GEMM_SMEM (NSTAGE * STAGE_SB)  // 122880 B

__global__ __launch_bounds__(256, 1) void gemm_tc(
    const __nv_bfloat16* __restrict__ Ah, const __nv_bfloat16* __restrict__ Al,
    const __nv_bfloat16* __restrict__ Bth, const __nv_bfloat16* __restrict__ Btl,
    float* __restrict__ C, int ldc, int K)
{
    extern __shared__ char smem[];
    const uint32_t sb = smem_u32(smem);
    const int tid = threadIdx.x;
    const int wid = tid >> 5, lane = tid & 31;
    const int row0 = blockIdx.y * 128, col0 = blockIdx.x * 128;

    const char* srcs[4] = {
        (const char*)(Ah  + (size_t)row0 * K),
        (const char*)(Al  + (size_t)row0 * K),
        (const char*)(Bth + (size_t)col0 * K),
        (const char*)(Btl + (size_t)col0 * K) };
    const size_t gpitch = (size_t)K * 2;

    const int nkt = K >> 5;                 // k-steps of 32

    auto issue = [&](int stage, int kt) {
        const uint32_t sbuf = sb + stage * STAGE_SB;
        const size_t kof = (size_t)kt * 64;
#pragma unroll
        for (int i = 0; i < 8; ++i) {
            int lin = i * 256 + tid;
            int t4 = lin >> 9, c = lin & 511;
            int row = c >> 2, kc = c & 3;
            const char* g = srcs[t4] + (size_t)row * gpitch + kof + kc * 16;
            uint32_t s = sbuf + t4 * TILE_SB + row * ROWB + kc * 16;
            CP_ASYNC16(s, g);
        }
    };

    const int wm = wid >> 1, wn = wid & 1;
    const int m0 = wm * 32, n0 = wn * 64;
    const int lrow = lane & 15, lsel = (lane >> 4) * 16;

    float acc[2][8][4];
#pragma unroll
    for (int mt = 0; mt < 2; ++mt)
#pragma unroll
        for (int nt = 0; nt < 8; ++nt)
#pragma unroll
            for (int j = 0; j < 4; ++j) acc[mt][nt][j] = 0.f;

    // prologue: stages 0, 1 in flight
    issue(0, 0); CP_COMMIT();
    issue(1, 1); CP_COMMIT();

    int stage = 0;
    for (int kt = 0; kt < nkt; ++kt) {
        if (kt + 2 < nkt) { CP_WAIT(1); } else { CP_WAIT(0); }
        __syncthreads();                 // stage kt resident; prior readers of
                                         // buffer (kt+2)%3 are done

        if (kt + 2 < nkt) {
            issue(stage == 0 ? 2 : stage - 1, kt + 2);   // (kt+2) % 3
            CP_COMMIT();
        }

        const uint32_t tb = sb + stage * STAGE_SB;
        const uint32_t A_h = tb, A_l = tb + TILE_SB;
        const uint32_t B_h = tb + 2 * TILE_SB, B_l = tb + 3 * TILE_SB;

#pragma unroll
        for (int kh = 0; kh < 2; ++kh) {
            const uint32_t kb = kh * 32 + lsel;

            uint32_t ah[2][4], al[2][4];
#pragma unroll
            for (int mt = 0; mt < 2; ++mt) {
                uint32_t ra = (m0 + mt * 16 + lrow) * ROWB + kb;
                LDSM4(ah[mt], A_h + ra);
                LDSM4(al[mt], A_l + ra);
            }
            uint32_t bh[8][2], bl[8][2];
#pragma unroll
            for (int p = 0; p < 4; ++p) {
                uint32_t rb = (n0 + p * 16 + lrow) * ROWB + kb;
                uint32_t t[4];
                LDSM4(t, B_h + rb);
                bh[2*p][0] = t[0]; bh[2*p][1] = t[2];
                bh[2*p+1][0] = t[1]; bh[2*p+1][1] = t[3];
                LDSM4(t, B_l + rb);
                bl[2*p][0] = t[0]; bl[2*p][1] = t[2];
                bl[2*p+1][0] = t[1]; bl[2*p+1][1] = t[3];
            }
#pragma unroll
            for (int mt = 0; mt < 2; ++mt)
#pragma unroll
                for (int nt = 0; nt < 8; ++nt) {
                    MMA16816(acc[mt][nt], ah[mt], bh[nt]);
                    MMA16816(acc[mt][nt], ah[mt], bl[nt]);
                    MMA16816(acc[mt][nt], al[mt], bh[nt]);
                }
        }
        stage = (stage == NSTAGE - 1) ? 0 : stage + 1;
    }

    const int er = row0 + m0 + (lane >> 2);
    const int ec = col0 + n0 + (lane & 3) * 2;
#pragma unroll
    for (int mt = 0; mt < 2; ++mt)
#pragma unroll
        for (int nt = 0; nt < 8; ++nt) {
            float2 v01 = {acc[mt][nt][0], acc[mt][nt][1]};
            float2 v23 = {acc[mt][nt][2], acc[mt][nt][3]};
            float* p = C + (size_t)(er + mt * 16) * ldc + ec + nt * 8;
            *(float2*)p = v01;
            *(float2*)(p + 8 * ldc) = v23;
        }
}

// ---------------------------------------------------------------------------
// Fused flash attention (causal, +bias), HMMA split-bf16 both MMAs.
//   Grid: (LSEQ/128 [reversed for balance], BATCH*NHEAD). 256 thr, 8 warps.
//   Warp w owns q-rows [w*16, w*16+16). Per iter: 64-row K/V tile.
//   Outputs attention result directly as bf16 hi/lo for the out-proj GEMM.
// ---------------------------------------------------------------------------
#define FP 72                          // smem pitch in bf16 elems (144 B)
#define FPB 144
#define FA_QH 0
#define FA_QL (FA_QH + 128 * FPB)      // 18432
#define FA_KH (FA_QL + 128 * FPB)      // 36864
#define FA_KL (FA_KH + 64 * FPB)       // 46080
#define FA_VH (FA_KL + 64 * FPB)       // 55296
#define FA_VL (FA_VH + 64 * FPB)       // 64512
#define FA_SMEM (FA_VL + 64 * FPB)     // 73728

__global__ __launch_bounds__(256, 1) void fa_kernel(
    const float* __restrict__ qkv, const float* __restrict__ bias,
    __nv_bfloat16* __restrict__ oh, __nv_bfloat16* __restrict__ ol)
{
    extern __shared__ char smem[];
    const uint32_t sb = smem_u32(smem);
    __nv_bfloat16* sm = (__nv_bfloat16*)smem;

    const int tid = threadIdx.x;
    const int wid = tid >> 5, lane = tid & 31;
    const int qi = (gridDim.x - 1) - blockIdx.x;      // big tiles first
    const int z = blockIdx.y;
    const int b = z >> 4, h = z & 15;
    const int q0 = qi * 128;

    const float* Qg = qkv + ((size_t)b * LSEQ) * QKVLD + h * HDIM;

    // ---- load Q tile (scaled by 1/8, exact), split hi/lo into smem ----
#pragma unroll
    for (int i = 0; i < 8; ++i) {
        int lin = i * 256 + tid;
        int r = lin >> 4, c4 = lin & 15;
        float4 v = *(const float4*)(Qg + (size_t)(q0 + r) * QKVLD + c4 * 4);
        float x[4] = {v.x * 0.125f, v.y * 0.125f, v.z * 0.125f, v.w * 0.125f};
        __nv_bfloat16 hv[4], lv[4];
#pragma unroll
        for (int j = 0; j < 4; ++j) {
            hv[j] = __float2bfloat16(x[j]);
            lv[j] = __float2bfloat16(x[j] - __bfloat162float(hv[j]));
        }
        __nv_bfloat16* qh = sm + (FA_QH >> 1) + r * FP + c4 * 4;
        __nv_bfloat16* ql = sm + (FA_QL >> 1) + r * FP + c4 * 4;
        *(__nv_bfloat162*)(qh)     = __nv_bfloat162(hv[0], hv[1]);
        *(__nv_bfloat162*)(qh + 2) = __nv_bfloat162(hv[2], hv[3]);
        *(__nv_bfloat162*)(ql)     = __nv_bfloat162(lv[0], lv[1]);
        *(__nv_bfloat162*)(ql + 2) = __nv_bfloat162(lv[2], lv[3]);
    }

    // softmax state (each thread: rows r0, r0+8 of its warp's 16)
    float m0 = -1e30f, m1 = -1e30f, l0 = 0.f, l1 = 0.f;
    float o[8][4];
#pragma unroll
    for (int nt = 0; nt < 8; ++nt)
#pragma unroll
        for (int j = 0; j < 4; ++j) o[nt][j] = 0.f;

    const int lrow = lane & 15, lsel = (lane >> 4) * 16;
    const int rq0 = q0 + wid * 16 + (lane >> 2);   // global q row (lower)
    const float* biasr = bias + ((size_t)h * LSEQ + rq0) * LSEQ;

    const int njt = 2 * qi + 2;

    for (int jt = 0; jt < njt; ++jt) {
        const int k0 = jt * 64;
        __syncthreads();   // previous iter's smem reads done

        // ---- load K,V tiles: K split -> kh/kl; V split+transpose -> vh/vl ----
        const float* Kg = Qg + (size_t)k0 * QKVLD + DMODEL;
        const float* Vg = Kg + DMODEL;
#pragma unroll
        for (int i = 0; i < 4; ++i) {
            int lin = i * 256 + tid;
            int r = lin >> 4, c4 = lin & 15;
            float4 kv = *(const float4*)(Kg + (size_t)r * QKVLD + c4 * 4);
            float kx[4] = {kv.x, kv.y, kv.z, kv.w};
            __nv_bfloat16 hv[4], lv[4];
#pragma unroll
            for (int j = 0; j < 4; ++j) {
                hv[j] = __float2bfloat16(kx[j]);
                lv[j] = __float2bfloat16(kx[j] - __bfloat162float(hv[j]));
            }
            __nv_bfloat16* kh = sm + (FA_KH >> 1) + r * FP + c4 * 4;
            __nv_bfloat16* kl = sm + (FA_KL >> 1) + r * FP + c4 * 4;
            *(__nv_bfloat162*)(kh)     = __nv_bfloat162(hv[0], hv[1]);
            *(__nv_bfloat162*)(kh + 2) = __nv_bfloat162(hv[2], hv[3]);
            *(__nv_bfloat162*)(kl)     = __nv_bfloat162(lv[0], lv[1]);
            *(__nv_bfloat162*)(kl + 2) = __nv_bfloat162(lv[2], lv[3]);

            float4 vv = *(const float4*)(Vg + (size_t)r * QKVLD + c4 * 4);
            float vx[4] = {vv.x, vv.y, vv.z, vv.w};
#pragma unroll
            for (int j = 0; j < 4; ++j) {
                __nv_bfloat16 hh = __float2bfloat16(vx[j]);
                __nv_bfloat16 ll = __float2bfloat16(vx[j] - __bfloat162float(hh));
                int d = c4 * 4 + j;
                sm[(FA_VH >> 1) + d * FP + r] = hh;   // transposed: vt[d][k]
                sm[(FA_VL >> 1) + d * FP + r] = ll;
            }
        }
        __syncthreads();

        // ---- S = Qs @ K^T (3-term split) ----
        float s[8][4];
#pragma unroll
        for (int nt = 0; nt < 8; ++nt)
#pragma unroll
            for (int j = 0; j < 4; ++j) s[nt][j] = 0.f;

#pragma unroll
        for (int kc = 0; kc < 4; ++kc) {
            const uint32_t kb = kc * 32 + lsel;
            uint32_t ah4[4], al4[4];
            uint32_t ra = (wid * 16 + lrow) * FPB + kb;
            LDSM4(ah4, sb + FA_QH + ra);
            LDSM4(al4, sb + FA_QL + ra);

            uint32_t bh[8][2], bl[8][2];
#pragma unroll
            for (int p = 0; p < 4; ++p) {
                uint32_t rb = (p * 16 + lrow) * FPB + kb;
                uint32_t t[4];
                LDSM4(t, sb + FA_KH + rb);
                bh[2*p][0] = t[0]; bh[2*p][1] = t[2];
                bh[2*p+1][0] = t[1]; bh[2*p+1][1] = t[3];
                LDSM4(t, sb + FA_KL + rb);
                bl[2*p][0] = t[0]; bl[2*p][1] = t[2];
                bl[2*p+1][0] = t[1]; bl[2*p+1][1] = t[3];
            }
#pragma unroll
            for (int nt = 0; nt < 8; ++nt) {
                MMA16816(s[nt], ah4, bh[nt]);
                MMA16816(s[nt], ah4, bl[nt]);
                MMA16816(s[nt], al4, bh[nt]);
            }
        }

        // ---- + bias, causal mask ----
#pragma unroll
        for (int nt = 0; nt < 8; ++nt) {
            const int kc0 = k0 + nt * 8 + (lane & 3) * 2;
            float2 b0 = *(const float2*)(biasr + kc0);
            float2 b1 = *(const float2*)(biasr + 8 * LSEQ + kc0);
            s[nt][0] = (kc0     <= rq0) ? s[nt][0] + b0.x : -1e30f;
            s[nt][1] = (kc0 + 1 <= rq0) ? s[nt][1] + b0.y : -1e30f;
            s[nt][2] = (kc0     <= rq0 + 8) ? s[nt][2] + b1.x : -1e30f;
            s[nt][3] = (kc0 + 1 <= rq0 + 8) ? s[nt][3] + b1.y : -1e30f;
        }

        // ---- online softmax ----
        float tmax0 = -1e30f, tmax1 = -1e30f;
#pragma unroll
        for (int nt = 0; nt < 8; ++nt) {
            tmax0 = fmaxf(tmax0, fmaxf(s[nt][0], s[nt][1]));
            tmax1 = fmaxf(tmax1, fmaxf(s[nt][2], s[nt][3]));
        }
#pragma unroll
        for (int off = 1; off <= 2; off <<= 1) {
            tmax0 = fmaxf(tmax0, __shfl_xor_sync(0xFFFFFFFFu, tmax0, off));
            tmax1 = fmaxf(tmax1, __shfl_xor_sync(0xFFFFFFFFu, tmax1, off));
        }
        const float mn0 = fmaxf(m0, tmax0), mn1 = fmaxf(m1, tmax1);
        const float a0 = __expf(m0 - mn0), a1 = __expf(m1 - mn1);
        m0 = mn0; m1 = mn1;

        float rs0 = 0.f, rs1 = 0.f;
#pragma unroll
        for (int nt = 0; nt < 8; ++nt) {
            s[nt][0] = __expf(s[nt][0] - mn0);
            s[nt][1] = __expf(s[nt][1] - mn0);
            s[nt][2] = __expf(s[nt][2] - mn1);
            s[nt][3] = __expf(s[nt][3] - mn1);
            rs0 += s[nt][0] + s[nt][1];
            rs1 += s[nt][2] + s[nt][3];
        }
#pragma unroll
        for (int off = 1; off <= 2; off <<= 1) {
            rs0 += __shfl_xor_sync(0xFFFFFFFFu, rs0, off);
            rs1 += __shfl_xor_sync(0xFFFFFFFFu, rs1, off);
        }
        l0 = l0 * a0 + rs0;
        l1 = l1 * a1 + rs1;
#pragma unroll
        for (int nt = 0; nt < 8; ++nt) {
            o[nt][0] *= a0; o[nt][1] *= a0;
            o[nt][2] *= a1; o[nt][3] *= a1;
        }

        // ---- O += P @ V (3-term split; P hi/lo built per k-chunk) ----
#pragma unroll
        for (int kc = 0; kc < 4; ++kc) {
            uint32_t ph[4], pl[4];
            {
                float* t0 = s[2 * kc];
                float* t1 = s[2 * kc + 1];
                float r0a = t0[0] - __bfloat162float(__float2bfloat16(t0[0]));
                float r0b = t0[1] - __bfloat162float(__float2bfloat16(t0[1]));
                float r0c = t0[2] - __bfloat162float(__float2bfloat16(t0[2]));
                float r0d = t0[3] - __bfloat162float(__float2bfloat16(t0[3]));
                float r1a = t1[0] - __bfloat162float(__float2bfloat16(t1[0]));
                float r1b = t1[1] - __bfloat162float(__float2bfloat16(t1[1]));
                float r1c = t1[2] - __bfloat162float(__float2bfloat16(t1[2]));
                float r1d = t1[3] - __bfloat162float(__float2bfloat16(t1[3]));
                ph[0] = pack_bf16(t0[0], t0[1]); ph[1] = pack_bf16(t0[2], t0[3]);
                ph[2] = pack_bf16(t1[0], t1[1]); ph[3] = pack_bf16(t1[2], t1[3]);
                pl[0] = pack_bf16(r0a, r0b);     pl[1] = pack_bf16(r0c, r0d);
                pl[2] = pack_bf16(r1a, r1b);     pl[3] = pack_bf16(r1c, r1d);
            }
            const uint32_t kb = kc * 32 + lsel;
            uint32_t bh[8][2], bl[8][2];
#pragma unroll
            for (int p = 0; p < 4; ++p) {
                uint32_t rb = (p * 16 + lrow) * FPB + kb;
                uint32_t t[4];
                LDSM4(t, sb + FA_VH + rb);
                bh[2*p][0] = t[0]; bh[2*p][1] = t[2];
                bh[2*p+1][0] = t[1]; bh[2*p+1][1] = t[3];
                LDSM4(t, sb + FA_VL + rb);
                bl[2*p][0] = t[0]; bl[2*p][1] = t[2];
                bl[2*p+1][0] = t[1]; bl[2*p+1][1] = t[3];
            }
#pragma unroll
            for (int nt = 0; nt < 8; ++nt) {
                MMA16816(o[nt], ph, bh[nt]);
                MMA16816(o[nt], ph, bl[nt]);
                MMA16816(o[nt], pl, bh[nt]);
            }
        }
    }

    // ---- finalize: O /= l, write bf16 hi/lo [b, q, h*64+d] ----
    const float inv0 = 1.f / l0, inv1 = 1.f / l1;
    const size_t rbase = ((size_t)b * LSEQ + rq0) * DMODEL + h * HDIM;
#pragma unroll
    for (int nt = 0; nt < 8; ++nt) {
        const int c = nt * 8 + (lane & 3) * 2;
        float v0 = o[nt][0] * inv0, v1 = o[nt][1] * inv0;
        float v2 = o[nt][2] * inv1, v3 = o[nt][3] * inv1;
        __nv_bfloat16 h0 = __float2bfloat16(v0), h1 = __float2bfloat16(v1);
        __nv_bfloat16 h2 = __float2bfloat16(v2), h3 = __float2bfloat16(v3);
        *(__nv_bfloat162*)(oh + rbase + c) = __nv_bfloat162(h0, h1);
        *(__nv_bfloat162*)(ol + rbase + c) =
            __nv_bfloat162(__float2bfloat16(v0 - __bfloat162float(h0)),
                           __float2bfloat16(v1 - __bfloat162float(h1)));
        *(__nv_bfloat162*)(oh + rbase + 8 * DMODEL + c) = __nv_bfloat162(h2, h3);
        *(__nv_bfloat162*)(ol + rbase + 8 * DMODEL + c) =
            __nv_bfloat162(__float2bfloat16(v2 - __bfloat162float(h2)),
                           __float2bfloat16(v3 - __bfloat162float(h3)));
    }
}

// ---------------------------------------------------------------------------
// fp32 -> (hi, lo) bf16 split, elementwise (vectorized)
// ---------------------------------------------------------------------------
__global__ __launch_bounds__(256) void split_kernel(const float* __restrict__ in,
                                                    __nv_bfloat16* __restrict__ hi,
                                                    __nv_bfloat16* __restrict__ lo, int n4) {
    int i = blockIdx.x * 256 + threadIdx.x;
    if (i >= n4) return;
    float4 v = ((const float4*)in)[i];
    float x[4] = {v.x, v.y, v.z, v.w};
    __nv_bfloat16 h[4], l[4];
#pragma unroll
    for (int j = 0; j < 4; ++j) {
        h[j] = __float2bfloat16(x[j]);
        l[j] = __float2bfloat16(x[j] - __bfloat162float(h[j]));
    }
    ((__nv_bfloat162*)hi)[i * 2 + 0] = __nv_bfloat162(h[0], h[1]);
    ((__nv_bfloat162*)hi)[i * 2 + 1] = __nv_bfloat162(h[2], h[3]);
    ((__nv_bfloat162*)lo)[i * 2 + 0] = __nv_bfloat162(l[0], l[1]);
    ((__nv_bfloat162*)lo)[i * 2 + 1] = __nv_bfloat162(l[2], l[3]);
}

// ---------------------------------------------------------------------------
// fp32 [R,C] -> bf16 hi/lo [C,R]  (transpose + split)
// ---------------------------------------------------------------------------
__global__ __launch_bounds__(256) void transpose_split(const float* __restrict__ in,
                                                       __nv_bfloat16* __restrict__ hi,
                                                       __nv_bfloat16* __restrict__ lo,
                                                       int R, int C) {
    __shared__ float t[32][33];
    const int c0 = blockIdx.x * 32, r0 = blockIdx.y * 32;
    const int tx = threadIdx.x, ty = threadIdx.y;
    for (int j = ty; j < 32; j += 8)
        t[j][tx] = in[(size_t)(r0 + j) * C + c0 + tx];
    __syncthreads();
    for (int j = ty; j < 32; j += 8) {
        float v = t[tx][j];
        __nv_bfloat16 h = __float2bfloat16(v);
        __nv_bfloat16 l = __float2bfloat16(v - __bfloat162float(h));
        size_t o = (size_t)(c0 + j) * R + r0 + tx;
        hi[o] = h; lo[o] = l;
    }
}

// ---------------------------------------------------------------------------
// Launch pipeline
// Inputs: x, mask(ignored: causal), w_qkv, w_out, rel_pos_bias
// ---------------------------------------------------------------------------
extern "C" void kernel_launch(void* const* d_in, const int* in_sizes, int n_in,
                              void* d_out, int out_size) {
    const float* x     = (const float*)d_in[0];
    const float* w_qkv = (const float*)d_in[2];
    const float* w_out = (const float*)d_in[3];
    const float* bias  = (const float*)d_in[4];

    float* qkv_p;
    cudaGetSymbolAddress((void**)&qkv_p, g_qkv);
    __nv_bfloat16 *ah, *al, *oh, *ol, *wqh, *wql, *woh, *wol;
    cudaGetSymbolAddress((void**)&ah, g_ah);   cudaGetSymbolAddress((void**)&al, g_al);
    cudaGetSymbolAddress((void**)&oh, g_oh);   cudaGetSymbolAddress((void**)&ol, g_ol);
    cudaGetSymbolAddress((void**)&wqh, g_wqh); cudaGetSymbolAddress((void**)&wql, g_wql);
    cudaGetSymbolAddress((void**)&woh, g_woh); cudaGetSymbolAddress((void**)&wol, g_wol);

    cudaFuncSetAttribute(gemm_tc, cudaFuncAttributeMaxDynamicSharedMemorySize, GEMM_SMEM);
    cudaFuncSetAttribute(fa_kernel, cudaFuncAttributeMaxDynamicSharedMemorySize, FA_SMEM);

    const int nx4 = (BATCH * LSEQ * DMODEL) / 4;

    // 0) convert operands
    split_kernel<<<(nx4 + 255) / 256, 256>>>(x, ah, al, nx4);
    transpose_split<<<dim3(QKVLD / 32, DMODEL / 32), dim3(32, 8)>>>(w_qkv, wqh, wql, DMODEL, QKVLD);
    transpose_split<<<dim3(DMODEL / 32, DMODEL / 32), dim3(32, 8)>>>(w_out, woh, wol, DMODEL, DMODEL);

    // 1) QKV projection (tensor cores): [4096,1024] @ [1024,3072]
    gemm_tc<<<dim3(QKVLD / 128, (BATCH * LSEQ) / 128), 256, GEMM_SMEM>>>(
        ah, al, wqh, wql, qkv_p, QKVLD, DMODEL);

    // 2) Fused flash attention (scores+bias+softmax+AV), writes bf16 hi/lo
    fa_kernel<<<dim3(LSEQ / 128, BATCH * NHEAD), 256, FA_SMEM>>>(qkv_p, bias, oh, ol);

    // 3) Output projection (tensor cores): [4096,1024] @ [1024,1024]
    gemm_tc<<<dim3(DMODEL / 128, (BATCH * LSEQ) / 128), 256, GEMM_SMEM>>>(
        oh, ol, woh, wol, (float*)d_out, DMODEL, DMODEL);
}

// round 17
// speedup vs baseline: 1.0781x; 1.0781x over previous
#include <cuda_runtime.h>
#include <cuda_bf16.h>
#include <cstdint>

// Problem constants
#define BATCH 4
#define LSEQ  1024
#define DMODEL 1024
#define NHEAD 16
#define HDIM  64
#define QKVLD (3 * DMODEL)   // 3072

// ---------------------------------------------------------------------------
// Scratch (device globals — allocation-free kernel_launch)
// ---------------------------------------------------------------------------
__device__ float g_qkv[(size_t)BATCH * LSEQ * 3 * DMODEL];        // 50 MB

// split-bf16 operands for tensor-core GEMMs
__device__ __nv_bfloat16 g_ah[(size_t)BATCH * LSEQ * DMODEL];     // x hi
__device__ __nv_bfloat16 g_al[(size_t)BATCH * LSEQ * DMODEL];     // x lo
__device__ __nv_bfloat16 g_oh[(size_t)BATCH * LSEQ * DMODEL];     // attn out hi (written by fa)
__device__ __nv_bfloat16 g_ol[(size_t)BATCH * LSEQ * DMODEL];     // attn out lo
__device__ __nv_bfloat16 g_wqh[(size_t)QKVLD * DMODEL];           // w_qkv^T hi  [3072,1024]
__device__ __nv_bfloat16 g_wql[(size_t)QKVLD * DMODEL];           // w_qkv^T lo
__device__ __nv_bfloat16 g_woh[(size_t)DMODEL * DMODEL];          // w_out^T hi  [1024,1024]
__device__ __nv_bfloat16 g_wol[(size_t)DMODEL * DMODEL];          // w_out^T lo

// ---------------------------------------------------------------------------
// PTX helpers — ONLY non-arch-'a' features (ldmatrix / mma.sync / cp.async)
// ---------------------------------------------------------------------------
__device__ __forceinline__ uint32_t smem_u32(const void* p) {
    uint32_t a;
    asm("{ .reg .u64 t; cvta.to.shared.u64 t, %1; cvt.u32.u64 %0, t; }" : "=r"(a) : "l"(p));
    return a;
}

#define CP_ASYNC16(s, g) \
    asm volatile("cp.async.cg.shared.global [%0], [%1], 16;" :: "r"(s), "l"(g))
#define CP_COMMIT() asm volatile("cp.async.commit_group;" ::: "memory")
#define CP_WAIT(n)  asm volatile("cp.async.wait_group %0;" :: "n"(n) : "memory")

#define LDSM4(r, addr)                                                       \
    asm volatile("ldmatrix.sync.aligned.m8n8.x4.shared.b16 {%0,%1,%2,%3}, [%4];" \
        : "=r"((r)[0]), "=r"((r)[1]), "=r"((r)[2]), "=r"((r)[3]) : "r"(addr))

#define MMA16816(d, a, b)                                                    \
    asm volatile("mma.sync.aligned.m16n8k16.row.col.f32.bf16.bf16.f32 "      \
        "{%0,%1,%2,%3}, {%4,%5,%6,%7}, {%8,%9}, {%0,%1,%2,%3};"              \
        : "+f"((d)[0]), "+f"((d)[1]), "+f"((d)[2]), "+f"((d)[3])             \
        : "r"((a)[0]), "r"((a)[1]), "r"((a)[2]), "r"((a)[3]),                \
          "r"((b)[0]), "r"((b)[1]))

__device__ __forceinline__ uint32_t pack_bf16(float a, float b) {
    __nv_bfloat162 h = __nv_bfloat162(__float2bfloat16(a), __float2bfloat16(b));
    return *(uint32_t*)&h;
}

// ---------------------------------------------------------------------------
// Tensor-core split-bf16 GEMM: C[M,N] = A[M,K] @ Bt[N,K]^T
//   2-stage cp.async pipeline (2 CTAs/SM), ONE __syncthreads per k-iter:
//     wait(stage kt) -> sync (readers of buf^1 done) -> issue(kt+1 into buf^1)
//     -> compute(buf).
//   CTA tile 128x128, BK=32, 8 warps (4x2), warp tile 32x64.
//   3-term split: Ah*Bh + Ah*Bl + Al*Bh
// ---------------------------------------------------------------------------
#define ROWB    80
#define TILE_SB (128 * ROWB)          // 10240 B per operand tile
#define BUF_SB  (4 * TILE_SB)         // Ah, Al, Bh, Bl = 40960 B
#define GEMM_SMEM (2 * BUF_SB)        // 81920 B -> 2 CTAs/SM

__global__ __launch_bounds__(256, 2) void gemm_tc(
    const __nv_bfloat16* __restrict__ Ah, const __nv_bfloat16* __restrict__ Al,
    const __nv_bfloat16* __restrict__ Bth, const __nv_bfloat16* __restrict__ Btl,
    float* __restrict__ C, int ldc, int K)
{
    extern __shared__ char smem[];
    const uint32_t sb = smem_u32(smem);
    const int tid = threadIdx.x;
    const int wid = tid >> 5, lane = tid & 31;
    const int row0 = blockIdx.y * 128, col0 = blockIdx.x * 128;

    const char* srcs[4] = {
        (const char*)(Ah  + (size_t)row0 * K),
        (const char*)(Al  + (size_t)row0 * K),
        (const char*)(Bth + (size_t)col0 * K),
        (const char*)(Btl + (size_t)col0 * K) };
    const size_t gpitch = (size_t)K * 2;

    const int nkt = K >> 5;                 // k-steps of 32

    auto issue = [&](int b, int kt) {
        const uint32_t sbuf = sb + b * BUF_SB;
        const size_t kof = (size_t)kt * 64;
#pragma unroll
        for (int i = 0; i < 8; ++i) {
            int lin = i * 256 + tid;
            int t4 = lin >> 9, c = lin & 511;
            int row = c >> 2, kc = c & 3;
            const char* g = srcs[t4] + (size_t)row * gpitch + kof + kc * 16;
            uint32_t s = sbuf + t4 * TILE_SB + row * ROWB + kc * 16;
            CP_ASYNC16(s, g);
        }
    };

    const int wm = wid >> 1, wn = wid & 1;
    const int m0 = wm * 32, n0 = wn * 64;
    const int lrow = lane & 15, lsel = (lane >> 4) * 16;

    float acc[2][8][4];
#pragma unroll
    for (int mt = 0; mt < 2; ++mt)
#pragma unroll
        for (int nt = 0; nt < 8; ++nt)
#pragma unroll
            for (int j = 0; j < 4; ++j) acc[mt][nt][j] = 0.f;

    issue(0, 0); CP_COMMIT();

    for (int kt = 0; kt < nkt; ++kt) {
        const int buf = kt & 1;
        CP_WAIT(0);              // stage kt landed
        __syncthreads();         // all readers of buf^1 (iter kt-1) finished

        if (kt + 1 < nkt) { issue(buf ^ 1, kt + 1); CP_COMMIT(); }

        const uint32_t tb = sb + buf * BUF_SB;
        const uint32_t A_h = tb, A_l = tb + TILE_SB;
        const uint32_t B_h = tb + 2 * TILE_SB, B_l = tb + 3 * TILE_SB;

#pragma unroll
        for (int kh = 0; kh < 2; ++kh) {
            const uint32_t kb = kh * 32 + lsel;

            uint32_t ah[2][4], al[2][4];
#pragma unroll
            for (int mt = 0; mt < 2; ++mt) {
                uint32_t ra = (m0 + mt * 16 + lrow) * ROWB + kb;
                LDSM4(ah[mt], A_h + ra);
                LDSM4(al[mt], A_l + ra);
            }
            uint32_t bh[8][2], bl[8][2];
#pragma unroll
            for (int p = 0; p < 4; ++p) {
                uint32_t rb = (n0 + p * 16 + lrow) * ROWB + kb;
                uint32_t t[4];
                LDSM4(t, B_h + rb);
                bh[2*p][0] = t[0]; bh[2*p][1] = t[2];
                bh[2*p+1][0] = t[1]; bh[2*p+1][1] = t[3];
                LDSM4(t, B_l + rb);
                bl[2*p][0] = t[0]; bl[2*p][1] = t[2];
                bl[2*p+1][0] = t[1]; bl[2*p+1][1] = t[3];
            }
#pragma unroll
            for (int mt = 0; mt < 2; ++mt)
#pragma unroll
                for (int nt = 0; nt < 8; ++nt) {
                    MMA16816(acc[mt][nt], ah[mt], bh[nt]);
                    MMA16816(acc[mt][nt], ah[mt], bl[nt]);
                    MMA16816(acc[mt][nt], al[mt], bh[nt]);
                }
        }
    }

    const int er = row0 + m0 + (lane >> 2);
    const int ec = col0 + n0 + (lane & 3) * 2;
#pragma unroll
    for (int mt = 0; mt < 2; ++mt)
#pragma unroll
        for (int nt = 0; nt < 8; ++nt) {
            float2 v01 = {acc[mt][nt][0], acc[mt][nt][1]};
            float2 v23 = {acc[mt][nt][2], acc[mt][nt][3]};
            float* p = C + (size_t)(er + mt * 16) * ldc + ec + nt * 8;
            *(float2*)p = v01;
            *(float2*)(p + 8 * ldc) = v23;
        }
}

// ---------------------------------------------------------------------------
// Fused flash attention (causal, +bias), HMMA split-bf16 both MMAs.
//   Grid: (LSEQ/128 [reversed for balance], BATCH*NHEAD). 256 thr, 8 warps.
//   Warp w owns q-rows [w*16, w*16+16). Per iter: 64-row K/V tile.
//   Outputs attention result directly as bf16 hi/lo for the out-proj GEMM.
// ---------------------------------------------------------------------------
#define FP 72                          // smem pitch in bf16 elems (144 B)
#define FPB 144
#define FA_QH 0
#define FA_QL (FA_QH + 128 * FPB)      // 18432
#define FA_KH (FA_QL + 128 * FPB)      // 36864
#define FA_KL (FA_KH + 64 * FPB)       // 46080
#define FA_VH (FA_KL + 64 * FPB)       // 55296
#define FA_VL (FA_VH + 64 * FPB)       // 64512
#define FA_SMEM (FA_VL + 64 * FPB)     // 73728

__global__ __launch_bounds__(256, 1) void fa_kernel(
    const float* __restrict__ qkv, const float* __restrict__ bias,
    __nv_bfloat16* __restrict__ oh, __nv_bfloat16* __restrict__ ol)
{
    extern __shared__ char smem[];
    const uint32_t sb = smem_u32(smem);
    __nv_bfloat16* sm = (__nv_bfloat16*)smem;

    const int tid = threadIdx.x;
    const int wid = tid >> 5, lane = tid & 31;
    const int qi = (gridDim.x - 1) - blockIdx.x;      // big tiles first
    const int z = blockIdx.y;
    const int b = z >> 4, h = z & 15;
    const int q0 = qi * 128;

    const float* Qg = qkv + ((size_t)b * LSEQ) * QKVLD + h * HDIM;

    // ---- load Q tile (scaled by 1/8, exact), split hi/lo into smem ----
#pragma unroll
    for (int i = 0; i < 8; ++i) {
        int lin = i * 256 + tid;
        int r = lin >> 4, c4 = lin & 15;
        float4 v = *(const float4*)(Qg + (size_t)(q0 + r) * QKVLD + c4 * 4);
        float x[4] = {v.x * 0.125f, v.y * 0.125f, v.z * 0.125f, v.w * 0.125f};
        __nv_bfloat16 hv[4], lv[4];
#pragma unroll
        for (int j = 0; j < 4; ++j) {
            hv[j] = __float2bfloat16(x[j]);
            lv[j] = __float2bfloat16(x[j] - __bfloat162float(hv[j]));
        }
        __nv_bfloat16* qh = sm + (FA_QH >> 1) + r * FP + c4 * 4;
        __nv_bfloat16* ql = sm + (FA_QL >> 1) + r * FP + c4 * 4;
        *(__nv_bfloat162*)(qh)     = __nv_bfloat162(hv[0], hv[1]);
        *(__nv_bfloat162*)(qh + 2) = __nv_bfloat162(hv[2], hv[3]);
        *(__nv_bfloat162*)(ql)     = __nv_bfloat162(lv[0], lv[1]);
        *(__nv_bfloat162*)(ql + 2) = __nv_bfloat162(lv[2], lv[3]);
    }

    // softmax state (each thread: rows r0, r0+8 of its warp's 16)
    float m0 = -1e30f, m1 = -1e30f, l0 = 0.f, l1 = 0.f;
    float o[8][4];
#pragma unroll
    for (int nt = 0; nt < 8; ++nt)
#pragma unroll
        for (int j = 0; j < 4; ++j) o[nt][j] = 0.f;

    const int lrow = lane & 15, lsel = (lane >> 4) * 16;
    const int rq0 = q0 + wid * 16 + (lane >> 2);   // global q row (lower)
    const float* biasr = bias + ((size_t)h * LSEQ + rq0) * LSEQ;

    const int njt = 2 * qi + 2;

    for (int jt = 0; jt < njt; ++jt) {
        const int k0 = jt * 64;
        __syncthreads();   // previous iter's smem reads done

        // ---- load K,V tiles: K split -> kh/kl; V split+transpose -> vh/vl ----
        const float* Kg = Qg + (size_t)k0 * QKVLD + DMODEL;
        const float* Vg = Kg + DMODEL;
#pragma unroll
        for (int i = 0; i < 4; ++i) {
            int lin = i * 256 + tid;
            int r = lin >> 4, c4 = lin & 15;
            float4 kv = *(const float4*)(Kg + (size_t)r * QKVLD + c4 * 4);
            float kx[4] = {kv.x, kv.y, kv.z, kv.w};
            __nv_bfloat16 hv[4], lv[4];
#pragma unroll
            for (int j = 0; j < 4; ++j) {
                hv[j] = __float2bfloat16(kx[j]);
                lv[j] = __float2bfloat16(kx[j] - __bfloat162float(hv[j]));
            }
            __nv_bfloat16* kh = sm + (FA_KH >> 1) + r * FP + c4 * 4;
            __nv_bfloat16* kl = sm + (FA_KL >> 1) + r * FP + c4 * 4;
            *(__nv_bfloat162*)(kh)     = __nv_bfloat162(hv[0], hv[1]);
            *(__nv_bfloat162*)(kh + 2) = __nv_bfloat162(hv[2], hv[3]);
            *(__nv_bfloat162*)(kl)     = __nv_bfloat162(lv[0], lv[1]);
            *(__nv_bfloat162*)(kl + 2) = __nv_bfloat162(lv[2], lv[3]);

            float4 vv = *(const float4*)(Vg + (size_t)r * QKVLD + c4 * 4);
            float vx[4] = {vv.x, vv.y, vv.z, vv.w};
#pragma unroll
            for (int j = 0; j < 4; ++j) {
                __nv_bfloat16 hh = __float2bfloat16(vx[j]);
                __nv_bfloat16 ll = __float2bfloat16(vx[j] - __bfloat162float(hh));
                int d = c4 * 4 + j;
                sm[(FA_VH >> 1) + d * FP + r] = hh;   // transposed: vt[d][k]
                sm[(FA_VL >> 1) + d * FP + r] = ll;
            }
        }
        __syncthreads();

        // ---- S = Qs @ K^T (3-term split) ----
        float s[8][4];
#pragma unroll
        for (int nt = 0; nt < 8; ++nt)
#pragma unroll
            for (int j = 0; j < 4; ++j) s[nt][j] = 0.f;

#pragma unroll
        for (int kc = 0; kc < 4; ++kc) {
            const uint32_t kb = kc * 32 + lsel;
            uint32_t ah4[4], al4[4];
            uint32_t ra = (wid * 16 + lrow) * FPB + kb;
            LDSM4(ah4, sb + FA_QH + ra);
            LDSM4(al4, sb + FA_QL + ra);

            uint32_t bh[8][2], bl[8][2];
#pragma unroll
            for (int p = 0; p < 4; ++p) {
                uint32_t rb = (p * 16 + lrow) * FPB + kb;
                uint32_t t[4];
                LDSM4(t, sb + FA_KH + rb);
                bh[2*p][0] = t[0]; bh[2*p][1] = t[2];
                bh[2*p+1][0] = t[1]; bh[2*p+1][1] = t[3];
                LDSM4(t, sb + FA_KL + rb);
                bl[2*p][0] = t[0]; bl[2*p][1] = t[2];
                bl[2*p+1][0] = t[1]; bl[2*p+1][1] = t[3];
            }
#pragma unroll
            for (int nt = 0; nt < 8; ++nt) {
                MMA16816(s[nt], ah4, bh[nt]);
                MMA16816(s[nt], ah4, bl[nt]);
                MMA16816(s[nt], al4, bh[nt]);
            }
        }

        // ---- + bias, causal mask ----
#pragma unroll
        for (int nt = 0; nt < 8; ++nt) {
            const int kc0 = k0 + nt * 8 + (lane & 3) * 2;
            float2 b0 = *(const float2*)(biasr + kc0);
            float2 b1 = *(const float2*)(biasr + 8 * LSEQ + kc0);
            s[nt][0] = (kc0     <= rq0) ? s[nt][0] + b0.x : -1e30f;
            s[nt][1] = (kc0 + 1 <= rq0) ? s[nt][1] + b0.y : -1e30f;
            s[nt][2] = (kc0     <= rq0 + 8) ? s[nt][2] + b1.x : -1e30f;
            s[nt][3] = (kc0 + 1 <= rq0 + 8) ? s[nt][3] + b1.y : -1e30f;
        }

        // ---- online softmax ----
        float tmax0 = -1e30f, tmax1 = -1e30f;
#pragma unroll
        for (int nt = 0; nt < 8; ++nt) {
            tmax0 = fmaxf(tmax0, fmaxf(s[nt][0], s[nt][1]));
            tmax1 = fmaxf(tmax1, fmaxf(s[nt][2], s[nt][3]));
        }
#pragma unroll
        for (int off = 1; off <= 2; off <<= 1) {
            tmax0 = fmaxf(tmax0, __shfl_xor_sync(0xFFFFFFFFu, tmax0, off));
            tmax1 = fmaxf(tmax1, __shfl_xor_sync(0xFFFFFFFFu, tmax1, off));
        }
        const float mn0 = fmaxf(m0, tmax0), mn1 = fmaxf(m1, tmax1);
        const float a0 = __expf(m0 - mn0), a1 = __expf(m1 - mn1);
        m0 = mn0; m1 = mn1;

        float rs0 = 0.f, rs1 = 0.f;
#pragma unroll
        for (int nt = 0; nt < 8; ++nt) {
            s[nt][0] = __expf(s[nt][0] - mn0);
            s[nt][1] = __expf(s[nt][1] - mn0);
            s[nt][2] = __expf(s[nt][2] - mn1);
            s[nt][3] = __expf(s[nt][3] - mn1);
            rs0 += s[nt][0] + s[nt][1];
            rs1 += s[nt][2] + s[nt][3];
        }
#pragma unroll
        for (int off = 1; off <= 2; off <<= 1) {
            rs0 += __shfl_xor_sync(0xFFFFFFFFu, rs0, off);
            rs1 += __shfl_xor_sync(0xFFFFFFFFu, rs1, off);
        }
        l0 = l0 * a0 + rs0;
        l1 = l1 * a1 + rs1;
#pragma unroll
        for (int nt = 0; nt < 8; ++nt) {
            o[nt][0] *= a0; o[nt][1] *= a0;
            o[nt][2] *= a1; o[nt][3] *= a1;
        }

        // ---- O += P @ V (3-term split; P hi/lo built per k-chunk) ----
#pragma unroll
        for (int kc = 0; kc < 4; ++kc) {
            uint32_t ph[4], pl[4];
            {
                float* t0 = s[2 * kc];
                float* t1 = s[2 * kc + 1];
                float r0a = t0[0] - __bfloat162float(__float2bfloat16(t0[0]));
                float r0b = t0[1] - __bfloat162float(__float2bfloat16(t0[1]));
                float r0c = t0[2] - __bfloat162float(__float2bfloat16(t0[2]));
                float r0d = t0[3] - __bfloat162float(__float2bfloat16(t0[3]));
                float r1a = t1[0] - __bfloat162float(__float2bfloat16(t1[0]));
                float r1b = t1[1] - __bfloat162float(__float2bfloat16(t1[1]));
                float r1c = t1[2] - __bfloat162float(__float2bfloat16(t1[2]));
                float r1d = t1[3] - __bfloat162float(__float2bfloat16(t1[3]));
                ph[0] = pack_bf16(t0[0], t0[1]); ph[1] = pack_bf16(t0[2], t0[3]);
                ph[2] = pack_bf16(t1[0], t1[1]); ph[3] = pack_bf16(t1[2], t1[3]);
                pl[0] = pack_bf16(r0a, r0b);     pl[1] = pack_bf16(r0c, r0d);
                pl[2] = pack_bf16(r1a, r1b);     pl[3] = pack_bf16(r1c, r1d);
            }
            const uint32_t kb = kc * 32 + lsel;
            uint32_t bh[8][2], bl[8][2];
#pragma unroll
            for (int p = 0; p < 4; ++p) {
                uint32_t rb = (p * 16 + lrow) * FPB + kb;
                uint32_t t[4];
                LDSM4(t, sb + FA_VH + rb);
                bh[2*p][0] = t[0]; bh[2*p][1] = t[2];
                bh[2*p+1][0] = t[1]; bh[2*p+1][1] = t[3];
                LDSM4(t, sb + FA_VL + rb);
                bl[2*p][0] = t[0]; bl[2*p][1] = t[2];
                bl[2*p+1][0] = t[1]; bl[2*p+1][1] = t[3];
            }
#pragma unroll
            for (int nt = 0; nt < 8; ++nt) {
                MMA16816(o[nt], ph, bh[nt]);
                MMA16816(o[nt], ph, bl[nt]);
                MMA16816(o[nt], pl, bh[nt]);
            }
        }
    }

    // ---- finalize: O /= l, write bf16 hi/lo [b, q, h*64+d] ----
    const float inv0 = 1.f / l0, inv1 = 1.f / l1;
    const size_t rbase = ((size_t)b * LSEQ + rq0) * DMODEL + h * HDIM;
#pragma unroll
    for (int nt = 0; nt < 8; ++nt) {
        const int c = nt * 8 + (lane & 3) * 2;
        float v0 = o[nt][0] * inv0, v1 = o[nt][1] * inv0;
        float v2 = o[nt][2] * inv1, v3 = o[nt][3] * inv1;
        __nv_bfloat16 h0 = __float2bfloat16(v0), h1 = __float2bfloat16(v1);
        __nv_bfloat16 h2 = __float2bfloat16(v2), h3 = __float2bfloat16(v3);
        *(__nv_bfloat162*)(oh + rbase + c) = __nv_bfloat162(h0, h1);
        *(__nv_bfloat162*)(ol + rbase + c) =
            __nv_bfloat162(__float2bfloat16(v0 - __bfloat162float(h0)),
                           __float2bfloat16(v1 - __bfloat162float(h1)));
        *(__nv_bfloat162*)(oh + rbase + 8 * DMODEL + c) = __nv_bfloat162(h2, h3);
        *(__nv_bfloat162*)(ol + rbase + 8 * DMODEL + c) =
            __nv_bfloat162(__float2bfloat16(v2 - __bfloat162float(h2)),
                           __float2bfloat16(v3 - __bfloat162float(h3)));
    }
}

// ---------------------------------------------------------------------------
// fp32 -> (hi, lo) bf16 split, elementwise (vectorized)
// ---------------------------------------------------------------------------
__global__ __launch_bounds__(256) void split_kernel(const float* __restrict__ in,
                                                    __nv_bfloat16* __restrict__ hi,
                                                    __nv_bfloat16* __restrict__ lo, int n4) {
    int i = blockIdx.x * 256 + threadIdx.x;
    if (i >= n4) return;
    float4 v = ((const float4*)in)[i];
    float x[4] = {v.x, v.y, v.z, v.w};
    __nv_bfloat16 h[4], l[4];
#pragma unroll
    for (int j = 0; j < 4; ++j) {
        h[j] = __float2bfloat16(x[j]);
        l[j] = __float2bfloat16(x[j] - __bfloat162float(h[j]));
    }
    ((__nv_bfloat162*)hi)[i * 2 + 0] = __nv_bfloat162(h[0], h[1]);
    ((__nv_bfloat162*)hi)[i * 2 + 1] = __nv_bfloat162(h[2], h[3]);
    ((__nv_bfloat162*)lo)[i * 2 + 0] = __nv_bfloat162(l[0], l[1]);
    ((__nv_bfloat162*)lo)[i * 2 + 1] = __nv_bfloat162(l[2], l[3]);
}

// ---------------------------------------------------------------------------
// fp32 [R,C] -> bf16 hi/lo [C,R]  (transpose + split)
// ---------------------------------------------------------------------------
__global__ __launch_bounds__(256) void transpose_split(const float* __restrict__ in,
                                                       __nv_bfloat16* __restrict__ hi,
                                                       __nv_bfloat16* __restrict__ lo,
                                                       int R, int C) {
    __shared__ float t[32][33];
    const int c0 = blockIdx.x * 32, r0 = blockIdx.y * 32;
    const int tx = threadIdx.x, ty = threadIdx.y;
    for (int j = ty; j < 32; j += 8)
        t[j][tx] = in[(size_t)(r0 + j) * C + c0 + tx];
    __syncthreads();
    for (int j = ty; j < 32; j += 8) {
        float v = t[tx][j];
        __nv_bfloat16 h = __float2bfloat16(v);
        __nv_bfloat16 l = __float2bfloat16(v - __bfloat162float(h));
        size_t o = (size_t)(c0 + j) * R + r0 + tx;
        hi[o] = h; lo[o] = l;
    }
}

// ---------------------------------------------------------------------------
// Launch pipeline
// Inputs: x, mask(ignored: causal), w_qkv, w_out, rel_pos_bias
// ---------------------------------------------------------------------------
extern "C" void kernel_launch(void* const* d_in, const int* in_sizes, int n_in,
                              void* d_out, int out_size) {
    const float* x     = (const float*)d_in[0];
    const float* w_qkv = (const float*)d_in[2];
    const float* w_out = (const float*)d_in[3];
    const float* bias  = (const float*)d_in[4];

    float* qkv_p;
    cudaGetSymbolAddress((void**)&qkv_p, g_qkv);
    __nv_bfloat16 *ah, *al, *oh, *ol, *wqh, *wql, *woh, *wol;
    cudaGetSymbolAddress((void**)&ah, g_ah);   cudaGetSymbolAddress((void**)&al, g_al);
    cudaGetSymbolAddress((void**)&oh, g_oh);   cudaGetSymbolAddress((void**)&ol, g_ol);
    cudaGetSymbolAddress((void**)&wqh, g_wqh); cudaGetSymbolAddress((void**)&wql, g_wql);
    cudaGetSymbolAddress((void**)&woh, g_woh); cudaGetSymbolAddress((void**)&wol, g_wol);

    cudaFuncSetAttribute(gemm_tc, cudaFuncAttributeMaxDynamicSharedMemorySize, GEMM_SMEM);
    cudaFuncSetAttribute(fa_kernel, cudaFuncAttributeMaxDynamicSharedMemorySize, FA_SMEM);

    const int nx4 = (BATCH * LSEQ * DMODEL) / 4;

    // 0) convert operands
    split_kernel<<<(nx4 + 255) / 256, 256>>>(x, ah, al, nx4);
    transpose_split<<<dim3(QKVLD / 32, DMODEL / 32), dim3(32, 8)>>>(w_qkv, wqh, wql, DMODEL, QKVLD);
    transpose_split<<<dim3(DMODEL / 32, DMODEL / 32), dim3(32, 8)>>>(w_out, woh, wol, DMODEL, DMODEL);

    // 1) QKV projection (tensor cores): [4096,1024] @ [1024,3072]
    gemm_tc<<<dim3(QKVLD / 128, (BATCH * LSEQ) / 128), 256, GEMM_SMEM>>>(
        ah, al, wqh, wql, qkv_p, QKVLD, DMODEL);

    // 2) Fused flash attention (scores+bias+softmax+AV), writes bf16 hi/lo
    fa_kernel<<<dim3(LSEQ / 128, BATCH * NHEAD), 256, FA_SMEM>>>(qkv_p, bias, oh, ol);

    // 3) Output projection (tensor cores): [4096,1024] @ [1024,1024]
    gemm_tc<<<dim3(DMODEL / 128, (BATCH * LSEQ) / 128), 256, GEMM_SMEM>>>(
        oh, ol, woh, wol, (float*)d_out, DMODEL, DMODEL);
}